// round 6
// baseline (speedup 1.0000x reference)
#include <cuda_runtime.h>

// Per-block f64 partial contributions to Pi = 0.5*U - W.
// Node blocks write -W_block at [0, nodeB); elem blocks write +0.5*U_block
// at [nodeB, nodeB+elemB). Each slot fully overwritten every replay.
__device__ double g_part[16384];

// 16B-aligned u_phys scratch: (u0, u1, u2, 0) per node. Static device array
// (allowed); sized for N_NODES = 1e6 with headroom.
__device__ float4 g_u[1048576];

__device__ __forceinline__ long long mk_i64(unsigned lo, unsigned hi) {
    return (long long)(((unsigned long long)hi << 32) | (unsigned long long)lo);
}

// Warp-reduce f32, then block-reduce f64. Valid result on thread 0.
__device__ __forceinline__ double block_reduce_f32_to_f64(float v) {
    #pragma unroll
    for (int o = 16; o > 0; o >>= 1)
        v += __shfl_xor_sync(0xffffffffu, v, o);
    __shared__ double sh[8];
    int lane = threadIdx.x & 31;
    int wid  = threadIdx.x >> 5;
    if (lane == 0) sh[wid] = (double)v;
    __syncthreads();
    double r = 0.0;
    if (wid == 0) {
        double t = (lane < 8) ? sh[lane] : 0.0;
        #pragma unroll
        for (int o = 4; o > 0; o >>= 1)
            t += __shfl_xor_sync(0xffffffffu, t, o);
        r = t;
    }
    return r;
}

// ---------------- node kernel: 4 nodes / thread ----------------
// u_phys -> out_u (scalar stores; +4B misaligned base) and g_u (float4).
// W partial -> g_part[blockIdx.x].
__global__ void __launch_bounds__(256) node_kernel(
        const float4* __restrict__ pred4,
        const float4* __restrict__ fext4,
        float* __restrict__ out_u,
        const float* __restrict__ ux_c,
        const float* __restrict__ uz_c,
        const float* __restrict__ th_c,
        int n_nodes) {
    const float s0 = ux_c[0], s1 = uz_c[0], s2 = th_c[0];
    int t = blockIdx.x * 256 + threadIdx.x;
    int n0 = 4 * t;
    float wacc = 0.0f;
    if (n0 + 3 < n_nodes) {
        float4 p0 = __ldcs(&pred4[3 * t + 0]);
        float4 p1 = __ldcs(&pred4[3 * t + 1]);
        float4 p2 = __ldcs(&pred4[3 * t + 2]);
        float4 f0 = __ldcs(&fext4[3 * t + 0]);
        float4 f1 = __ldcs(&fext4[3 * t + 1]);
        float4 f2 = __ldcs(&fext4[3 * t + 2]);

        float u[12];
        u[0]  = p0.x * s0; u[1]  = p0.y * s1; u[2]  = p0.z * s2;
        u[3]  = p0.w * s0; u[4]  = p1.x * s1; u[5]  = p1.y * s2;
        u[6]  = p1.z * s0; u[7]  = p1.w * s1; u[8]  = p2.x * s2;
        u[9]  = p2.y * s0; u[10] = p2.z * s1; u[11] = p2.w * s2;

        g_u[n0 + 0] = make_float4(u[0], u[1],  u[2],  0.0f);
        g_u[n0 + 1] = make_float4(u[3], u[4],  u[5],  0.0f);
        g_u[n0 + 2] = make_float4(u[6], u[7],  u[8],  0.0f);
        g_u[n0 + 3] = make_float4(u[9], u[10], u[11], 0.0f);

        float* o = out_u + 12 * (size_t)t;
        #pragma unroll
        for (int k = 0; k < 12; k++) __stcs(o + k, u[k]);

        wacc = f0.x * u[0] + f0.y * u[1]  + f0.z * u[2]  + f0.w * u[3]
             + f1.x * u[4] + f1.y * u[5]  + f1.z * u[6]  + f1.w * u[7]
             + f2.x * u[8] + f2.y * u[9]  + f2.z * u[10] + f2.w * u[11];
    } else if (n0 < n_nodes) {
        const float* pr = (const float*)pred4;
        const float* fe = (const float*)fext4;
        for (int n = n0; n < n_nodes; n++) {
            float a = pr[3 * (size_t)n + 0] * s0;
            float b = pr[3 * (size_t)n + 1] * s1;
            float c = pr[3 * (size_t)n + 2] * s2;
            g_u[n] = make_float4(a, b, c, 0.0f);
            out_u[3 * (size_t)n + 0] = a;
            out_u[3 * (size_t)n + 1] = b;
            out_u[3 * (size_t)n + 2] = c;
            wacc += fe[3 * (size_t)n] * a + fe[3 * (size_t)n + 1] * b
                  + fe[3 * (size_t)n + 2] * c;
        }
    }
    double bs = block_reduce_f32_to_f64(wacc);
    if (threadIdx.x == 0) g_part[blockIdx.x] = -bs;   // contributes -W
}

// ---------------- element kernel: 4 elements / thread ----------------
__global__ void __launch_bounds__(256) elem_kernel(
        const void* __restrict__ conn,
        const float* __restrict__ Lv,
        const float* __restrict__ Ev,
        const float* __restrict__ Av,
        const float* __restrict__ Iv,
        const float* __restrict__ dirs,
        int n_elem, int part_off, long long n_nodes) {

    // conn dtype probe (uniform per block; negligible cost).
    __shared__ int s_c64;
    if (threadIdx.x == 0) {
        const long long* c64 = (const long long*)conn;
        int ok = 1;
        #pragma unroll
        for (int k = 0; k < 8; k++) {
            long long v = c64[k];
            if (v < 0 || v >= n_nodes) ok = 0;
        }
        s_c64 = ok;
    }
    __syncthreads();
    const int conn64 = s_c64;

    int i = blockIdx.x * 256 + threadIdx.x;
    int e0 = 4 * i;
    float qacc = 0.0f;

    if (e0 < n_elem) {
        bool full = (e0 + 3 < n_elem);

        long long ia[4], ib[4];
        if (conn64) {
            if (full) {
                const uint4* c = (const uint4*)((const char*)conn + (size_t)e0 * 16);
                uint4 w0 = __ldcs(c + 0);
                uint4 w1 = __ldcs(c + 1);
                uint4 w2 = __ldcs(c + 2);
                uint4 w3 = __ldcs(c + 3);
                ia[0] = mk_i64(w0.x, w0.y); ib[0] = mk_i64(w0.z, w0.w);
                ia[1] = mk_i64(w1.x, w1.y); ib[1] = mk_i64(w1.z, w1.w);
                ia[2] = mk_i64(w2.x, w2.y); ib[2] = mk_i64(w2.z, w2.w);
                ia[3] = mk_i64(w3.x, w3.y); ib[3] = mk_i64(w3.z, w3.w);
            } else {
                const long long* c = (const long long*)conn;
                #pragma unroll
                for (int k = 0; k < 4; k++) {
                    int e = e0 + k;
                    if (e < n_elem) { ia[k] = c[2 * (size_t)e]; ib[k] = c[2 * (size_t)e + 1]; }
                    else            { ia[k] = 0; ib[k] = 0; }
                }
            }
        } else {
            if (full) {
                const uint4* c = (const uint4*)((const char*)conn + (size_t)e0 * 8);
                uint4 w0 = __ldcs(c + 0);
                uint4 w1 = __ldcs(c + 1);
                ia[0] = (int)w0.x; ib[0] = (int)w0.y;
                ia[1] = (int)w0.z; ib[1] = (int)w0.w;
                ia[2] = (int)w1.x; ib[2] = (int)w1.y;
                ia[3] = (int)w1.z; ib[3] = (int)w1.w;
            } else {
                const int* c = (const int*)conn;
                #pragma unroll
                for (int k = 0; k < 4; k++) {
                    int e = e0 + k;
                    if (e < n_elem) { ia[k] = c[2 * (size_t)e]; ib[k] = c[2 * (size_t)e + 1]; }
                    else            { ia[k] = 0; ib[k] = 0; }
                }
            }
        }

        // One 16B gather per node — L2-resident g_u, 1 wavefront-line per lane.
        float4 A[4], B[4];
        #pragma unroll
        for (int k = 0; k < 4; k++) {
            A[k] = g_u[ia[k]];
            B[k] = g_u[ib[k]];
        }

        float Lr[4], EAr[4], EIr[4], cr[4], sr[4];
        if (full) {
            float4 L4 = __ldcs((const float4*)(Lv + e0));
            float4 E4 = __ldcs((const float4*)(Ev + e0));
            float4 A4 = __ldcs((const float4*)(Av + e0));
            float4 I4 = __ldcs((const float4*)(Iv + e0));
            Lr[0]=L4.x; Lr[1]=L4.y; Lr[2]=L4.z; Lr[3]=L4.w;
            EAr[0]=E4.x*A4.x; EAr[1]=E4.y*A4.y; EAr[2]=E4.z*A4.z; EAr[3]=E4.w*A4.w;
            EIr[0]=E4.x*I4.x; EIr[1]=E4.y*I4.y; EIr[2]=E4.z*I4.z; EIr[3]=E4.w*I4.w;
            const float4* d4 = (const float4*)dirs;
            float4 v0 = __ldcs(&d4[3 * i + 0]);
            float4 v1 = __ldcs(&d4[3 * i + 1]);
            float4 v2 = __ldcs(&d4[3 * i + 2]);
            cr[0]=v0.x; sr[0]=v0.z;
            cr[1]=v0.w; sr[1]=v1.y;
            cr[2]=v1.z; sr[2]=v2.x;
            cr[3]=v2.y; sr[3]=v2.w;
        } else {
            #pragma unroll
            for (int k = 0; k < 4; k++) {
                int e = e0 + k;
                if (e < n_elem) {
                    float E = Ev[e];
                    Lr[k]  = Lv[e];
                    EAr[k] = E * Av[e];
                    EIr[k] = E * Iv[e];
                    cr[k]  = dirs[3 * (size_t)e + 0];
                    sr[k]  = dirs[3 * (size_t)e + 2];
                } else {
                    Lr[k] = 1.0f; EAr[k] = 0.0f; EIr[k] = 0.0f; cr[k] = 1.0f; sr[k] = 0.0f;
                }
            }
        }

        #pragma unroll
        for (int k = 0; k < 4; k++) {
            float c = cr[k], s = sr[k];
            float u_A =  c * A[k].x + s * A[k].y;
            float w_A = -s * A[k].x + c * A[k].y;
            float t_A = -A[k].z;
            float u_B =  c * B[k].x + s * B[k].y;
            float w_B = -s * B[k].x + c * B[k].y;
            float t_B = -B[k].z;

            float inv   = __fdividef(1.0f, Lr[k]);
            float ea_l  = EAr[k] * inv;
            float ei_l  = EIr[k] * inv;
            float ei_l2 = ei_l * inv;
            float ei_l3 = ei_l2 * inv;

            float du = u_A - u_B;
            float dw = w_A - w_B;
            float ts = t_A + t_B;

            float q = ea_l * du * du
                    + 12.0f * ei_l3 * dw * dw
                    + 12.0f * ei_l2 * dw * ts
                    + 4.0f * ei_l * (t_A * t_A + t_B * t_B + t_A * t_B);
            if (e0 + k < n_elem) qacc += q;
        }
    }

    double bs = block_reduce_f32_to_f64(qacc);
    if (threadIdx.x == 0) g_part[part_off + blockIdx.x] = 0.5 * bs;  // +0.5*U
}

// ---------------- final: reduce partials, normalize ----------------
__global__ void __launch_bounds__(1024) final_kernel(
        float* __restrict__ out,
        const float* __restrict__ ux_c,
        const float* __restrict__ F_c,
        int total_blocks) {
    double acc = 0.0;
    for (int k = threadIdx.x; k < total_blocks; k += 1024)
        acc += g_part[k];
    #pragma unroll
    for (int o = 16; o > 0; o >>= 1)
        acc += __shfl_xor_sync(0xffffffffu, acc, o);
    __shared__ double sh[32];
    int lane = threadIdx.x & 31;
    int wid  = threadIdx.x >> 5;
    if (lane == 0) sh[wid] = acc;
    __syncthreads();
    if (wid == 0) {
        double t = (lane < 32) ? sh[lane] : 0.0;
        #pragma unroll
        for (int o = 16; o > 0; o >>= 1)
            t += __shfl_xor_sync(0xffffffffu, t, o);
        if (lane == 0) {
            double E_c = fmax((double)(F_c[0] * ux_c[0]), 1e-30);
            out[0] = (float)(t / E_c);
        }
    }
}

extern "C" void kernel_launch(void* const* d_in, const int* in_sizes, int n_in,
                              void* d_out, int out_size) {
    const float* pred  = (const float*)d_in[0];    // (N_NODES, 3)
    const float* fext  = (const float*)d_in[1];    // (N_NODES, 3)
    const void*  conn  = d_in[2];                  // (N_ELEM, 2) int64 or int32
    const float* Lv    = (const float*)d_in[3];
    const float* Ev    = (const float*)d_in[4];
    const float* Av    = (const float*)d_in[5];
    const float* Iv    = (const float*)d_in[6];
    const float* dirs  = (const float*)d_in[7];    // (N_ELEM, 3)
    const float* ux_c  = (const float*)d_in[8];
    const float* uz_c  = (const float*)d_in[9];
    const float* th_c  = (const float*)d_in[10];
    const float* F_c   = (const float*)d_in[11];

    float* out = (float*)d_out;   // [0] = Pi_norm, [1..3N] = u_phys flat

    int n_flat  = in_sizes[0];                // 3 * N_NODES
    int n_nodes = n_flat / 3;
    int n_elem  = in_sizes[3];                // N_ELEM

    int node_blocks = (n_nodes + 4 * 256 - 1) / (4 * 256);  // 4 nodes / thread
    int elem_blocks = (n_elem + 4 * 256 - 1) / (4 * 256);   // 4 elems / thread
    int total_blocks = node_blocks + elem_blocks;

    node_kernel<<<node_blocks, 256>>>((const float4*)pred, (const float4*)fext,
                                      out + 1, ux_c, uz_c, th_c, n_nodes);
    elem_kernel<<<elem_blocks, 256>>>(conn, Lv, Ev, Av, Iv, dirs,
                                      n_elem, node_blocks, (long long)n_nodes);
    final_kernel<<<1, 1024>>>(out, ux_c, F_c, total_blocks);
}

// round 7
// speedup vs baseline: 1.0827x; 1.0827x over previous
#include <cuda_runtime.h>

// Per-block f64 partial contributions to Pi = 0.5*U - W.
__device__ double g_part[16384];

// 16B-aligned u_phys scratch: (u0, u1, u2, 0) per node.
__device__ float4 g_u[1048576];

__device__ __forceinline__ long long mk_i64(unsigned lo, unsigned hi) {
    return (long long)(((unsigned long long)hi << 32) | (unsigned long long)lo);
}

// Warp-reduce f32, then block-reduce f64. Valid result on thread 0.
__device__ __forceinline__ double block_reduce_f32_to_f64(float v) {
    #pragma unroll
    for (int o = 16; o > 0; o >>= 1)
        v += __shfl_xor_sync(0xffffffffu, v, o);
    __shared__ double sh[8];
    int lane = threadIdx.x & 31;
    int wid  = threadIdx.x >> 5;
    if (lane == 0) sh[wid] = (double)v;
    __syncthreads();
    double r = 0.0;
    if (wid == 0) {
        double t = (lane < 8) ? sh[lane] : 0.0;
        #pragma unroll
        for (int o = 4; o > 0; o >>= 1)
            t += __shfl_xor_sync(0xffffffffu, t, o);
        r = t;
    }
    return r;
}

// ---------------- node kernel: 256 nodes / block, fully coalesced ----------------
// Each thread does 3 coalesced scalar loads/stores (stride 256 within block),
// stages u in smem, then writes g_u[node] as one coalesced float4.
__global__ void __launch_bounds__(256) node_kernel(
        const float* __restrict__ pred,
        const float* __restrict__ fext,
        float* __restrict__ out_u,
        const float* __restrict__ ux_c,
        const float* __restrict__ uz_c,
        const float* __restrict__ th_c,
        int n_flat, int n_nodes) {
    const float s0 = ux_c[0], s1 = uz_c[0], s2 = th_c[0];
    const int tid = threadIdx.x;
    __shared__ float su[768];

    size_t base = (size_t)blockIdx.x * 768;
    float wacc = 0.0f;
    #pragma unroll
    for (int k = 0; k < 3; k++) {
        size_t idx = base + k * 256 + tid;
        if (idx < (size_t)n_flat) {
            int m = (int)(idx % 3);
            float sc = (m == 0) ? s0 : ((m == 1) ? s1 : s2);
            float u = __ldcs(pred + idx) * sc;
            su[k * 256 + tid] = u;
            __stcs(out_u + idx, u);
            wacc += __ldcs(fext + idx) * u;
        }
    }
    __syncthreads();

    int j = blockIdx.x * 256 + tid;     // node index
    if (j < n_nodes) {
        g_u[j] = make_float4(su[3 * tid], su[3 * tid + 1], su[3 * tid + 2], 0.0f);
    }

    double bs = block_reduce_f32_to_f64(wacc);
    if (tid == 0) g_part[blockIdx.x] = -bs;   // contributes -W
}

// ---------------- element kernel: 4 elements / thread ----------------
__global__ void __launch_bounds__(256) elem_kernel(
        const void* __restrict__ conn,
        const float* __restrict__ Lv,
        const float* __restrict__ Ev,
        const float* __restrict__ Av,
        const float* __restrict__ Iv,
        const float* __restrict__ dirs,
        int n_elem, int part_off, long long n_nodes) {

    // conn dtype probe (uniform per block; negligible cost).
    __shared__ int s_c64;
    if (threadIdx.x == 0) {
        const long long* c64 = (const long long*)conn;
        int ok = 1;
        #pragma unroll
        for (int k = 0; k < 8; k++) {
            long long v = c64[k];
            if (v < 0 || v >= n_nodes) ok = 0;
        }
        s_c64 = ok;
    }
    __syncthreads();
    const int conn64 = s_c64;

    int i = blockIdx.x * 256 + threadIdx.x;
    int e0 = 4 * i;
    float qacc = 0.0f;

    if (e0 < n_elem) {
        bool full = (e0 + 3 < n_elem);

        long long ia[4], ib[4];
        if (conn64) {
            if (full) {
                const uint4* c = (const uint4*)((const char*)conn + (size_t)e0 * 16);
                uint4 w0 = __ldcs(c + 0);
                uint4 w1 = __ldcs(c + 1);
                uint4 w2 = __ldcs(c + 2);
                uint4 w3 = __ldcs(c + 3);
                ia[0] = mk_i64(w0.x, w0.y); ib[0] = mk_i64(w0.z, w0.w);
                ia[1] = mk_i64(w1.x, w1.y); ib[1] = mk_i64(w1.z, w1.w);
                ia[2] = mk_i64(w2.x, w2.y); ib[2] = mk_i64(w2.z, w2.w);
                ia[3] = mk_i64(w3.x, w3.y); ib[3] = mk_i64(w3.z, w3.w);
            } else {
                const long long* c = (const long long*)conn;
                #pragma unroll
                for (int k = 0; k < 4; k++) {
                    int e = e0 + k;
                    if (e < n_elem) { ia[k] = c[2 * (size_t)e]; ib[k] = c[2 * (size_t)e + 1]; }
                    else            { ia[k] = 0; ib[k] = 0; }
                }
            }
        } else {
            if (full) {
                const uint4* c = (const uint4*)((const char*)conn + (size_t)e0 * 8);
                uint4 w0 = __ldcs(c + 0);
                uint4 w1 = __ldcs(c + 1);
                ia[0] = (int)w0.x; ib[0] = (int)w0.y;
                ia[1] = (int)w0.z; ib[1] = (int)w0.w;
                ia[2] = (int)w1.x; ib[2] = (int)w1.y;
                ia[3] = (int)w1.z; ib[3] = (int)w1.w;
            } else {
                const int* c = (const int*)conn;
                #pragma unroll
                for (int k = 0; k < 4; k++) {
                    int e = e0 + k;
                    if (e < n_elem) { ia[k] = c[2 * (size_t)e]; ib[k] = c[2 * (size_t)e + 1]; }
                    else            { ia[k] = 0; ib[k] = 0; }
                }
            }
        }

        // One 16B gather per node endpoint (g_u is L2-resident).
        float4 A[4], B[4];
        #pragma unroll
        for (int k = 0; k < 4; k++) {
            A[k] = g_u[ia[k]];
            B[k] = g_u[ib[k]];
        }

        float Lr[4], EAr[4], EIr[4], cr[4], sr[4];
        if (full) {
            float4 L4 = __ldcs((const float4*)(Lv + e0));
            float4 E4 = __ldcs((const float4*)(Ev + e0));
            float4 A4 = __ldcs((const float4*)(Av + e0));
            float4 I4 = __ldcs((const float4*)(Iv + e0));
            Lr[0]=L4.x; Lr[1]=L4.y; Lr[2]=L4.z; Lr[3]=L4.w;
            EAr[0]=E4.x*A4.x; EAr[1]=E4.y*A4.y; EAr[2]=E4.z*A4.z; EAr[3]=E4.w*A4.w;
            EIr[0]=E4.x*I4.x; EIr[1]=E4.y*I4.y; EIr[2]=E4.z*I4.z; EIr[3]=E4.w*I4.w;
            const float4* d4 = (const float4*)dirs;
            float4 v0 = __ldcs(&d4[3 * i + 0]);
            float4 v1 = __ldcs(&d4[3 * i + 1]);
            float4 v2 = __ldcs(&d4[3 * i + 2]);
            cr[0]=v0.x; sr[0]=v0.z;
            cr[1]=v0.w; sr[1]=v1.y;
            cr[2]=v1.z; sr[2]=v2.x;
            cr[3]=v2.y; sr[3]=v2.w;
        } else {
            #pragma unroll
            for (int k = 0; k < 4; k++) {
                int e = e0 + k;
                if (e < n_elem) {
                    float E = Ev[e];
                    Lr[k]  = Lv[e];
                    EAr[k] = E * Av[e];
                    EIr[k] = E * Iv[e];
                    cr[k]  = dirs[3 * (size_t)e + 0];
                    sr[k]  = dirs[3 * (size_t)e + 2];
                } else {
                    Lr[k] = 1.0f; EAr[k] = 0.0f; EIr[k] = 0.0f; cr[k] = 1.0f; sr[k] = 0.0f;
                }
            }
        }

        #pragma unroll
        for (int k = 0; k < 4; k++) {
            float c = cr[k], s = sr[k];
            float u_A =  c * A[k].x + s * A[k].y;
            float w_A = -s * A[k].x + c * A[k].y;
            float t_A = -A[k].z;
            float u_B =  c * B[k].x + s * B[k].y;
            float w_B = -s * B[k].x + c * B[k].y;
            float t_B = -B[k].z;

            float inv   = __fdividef(1.0f, Lr[k]);
            float ea_l  = EAr[k] * inv;
            float ei_l  = EIr[k] * inv;
            float ei_l2 = ei_l * inv;
            float ei_l3 = ei_l2 * inv;

            float du = u_A - u_B;
            float dw = w_A - w_B;
            float ts = t_A + t_B;

            float q = ea_l * du * du
                    + 12.0f * ei_l3 * dw * dw
                    + 12.0f * ei_l2 * dw * ts
                    + 4.0f * ei_l * (t_A * t_A + t_B * t_B + t_A * t_B);
            if (e0 + k < n_elem) qacc += q;
        }
    }

    double bs = block_reduce_f32_to_f64(qacc);
    if (threadIdx.x == 0) g_part[part_off + blockIdx.x] = 0.5 * bs;  // +0.5*U
}

// ---------------- final: reduce partials, normalize ----------------
__global__ void __launch_bounds__(1024) final_kernel(
        float* __restrict__ out,
        const float* __restrict__ ux_c,
        const float* __restrict__ F_c,
        int total_blocks) {
    double acc = 0.0;
    for (int k = threadIdx.x; k < total_blocks; k += 1024)
        acc += g_part[k];
    #pragma unroll
    for (int o = 16; o > 0; o >>= 1)
        acc += __shfl_xor_sync(0xffffffffu, acc, o);
    __shared__ double sh[32];
    int lane = threadIdx.x & 31;
    int wid  = threadIdx.x >> 5;
    if (lane == 0) sh[wid] = acc;
    __syncthreads();
    if (wid == 0) {
        double t = sh[lane];
        #pragma unroll
        for (int o = 16; o > 0; o >>= 1)
            t += __shfl_xor_sync(0xffffffffu, t, o);
        if (lane == 0) {
            double E_c = fmax((double)(F_c[0] * ux_c[0]), 1e-30);
            out[0] = (float)(t / E_c);
        }
    }
}

extern "C" void kernel_launch(void* const* d_in, const int* in_sizes, int n_in,
                              void* d_out, int out_size) {
    const float* pred  = (const float*)d_in[0];    // (N_NODES, 3)
    const float* fext  = (const float*)d_in[1];    // (N_NODES, 3)
    const void*  conn  = d_in[2];                  // (N_ELEM, 2) int64 or int32
    const float* Lv    = (const float*)d_in[3];
    const float* Ev    = (const float*)d_in[4];
    const float* Av    = (const float*)d_in[5];
    const float* Iv    = (const float*)d_in[6];
    const float* dirs  = (const float*)d_in[7];    // (N_ELEM, 3)
    const float* ux_c  = (const float*)d_in[8];
    const float* uz_c  = (const float*)d_in[9];
    const float* th_c  = (const float*)d_in[10];
    const float* F_c   = (const float*)d_in[11];

    float* out = (float*)d_out;   // [0] = Pi_norm, [1..3N] = u_phys flat

    int n_flat  = in_sizes[0];                // 3 * N_NODES
    int n_nodes = n_flat / 3;
    int n_elem  = in_sizes[3];                // N_ELEM

    int node_blocks = (n_nodes + 255) / 256;               // 256 nodes / block
    int elem_blocks = (n_elem + 4 * 256 - 1) / (4 * 256);  // 4 elems / thread
    int total_blocks = node_blocks + elem_blocks;

    node_kernel<<<node_blocks, 256>>>(pred, fext, out + 1,
                                      ux_c, uz_c, th_c, n_flat, n_nodes);
    elem_kernel<<<elem_blocks, 256>>>(conn, Lv, Ev, Av, Iv, dirs,
                                      n_elem, node_blocks, (long long)n_nodes);
    final_kernel<<<1, 1024>>>(out, ux_c, F_c, total_blocks);
}

// round 8
// speedup vs baseline: 1.2346x; 1.1404x over previous
#include <cuda_runtime.h>

// Per-block f64 partial contributions to Pi = 0.5*U - W.
__device__ double g_part[16384];

// 16B-aligned u_phys scratch: (u0, u1, u2, 0) per node.
__device__ float4 g_u[1048576];

__device__ __forceinline__ long long mk_i64(unsigned lo, unsigned hi) {
    return (long long)(((unsigned long long)hi << 32) | (unsigned long long)lo);
}

// Warp-reduce f32, then block-reduce f64. Valid result on thread 0.
__device__ __forceinline__ double block_reduce_f32_to_f64(float v) {
    #pragma unroll
    for (int o = 16; o > 0; o >>= 1)
        v += __shfl_xor_sync(0xffffffffu, v, o);
    __shared__ double sh[8];
    int lane = threadIdx.x & 31;
    int wid  = threadIdx.x >> 5;
    if (lane == 0) sh[wid] = (double)v;
    __syncthreads();
    double r = 0.0;
    if (wid == 0) {
        double t = (lane < 8) ? sh[lane] : 0.0;
        #pragma unroll
        for (int o = 4; o > 0; o >>= 1)
            t += __shfl_xor_sync(0xffffffffu, t, o);
        r = t;
    }
    return r;
}

// ---------------- node kernel: 3072 floats (1024 nodes) / block ----------------
// 6x LDG.128 per thread (pred + fext), u staged in smem, coalesced stores.
__global__ void __launch_bounds__(256) node_kernel(
        const float4* __restrict__ pred4,
        const float4* __restrict__ fext4,
        float* __restrict__ out_u,
        const float* __restrict__ ux_c,
        const float* __restrict__ uz_c,
        const float* __restrict__ th_c,
        int n_flat, int n_nodes) {
    const float s0 = ux_c[0], s1 = uz_c[0], s2 = th_c[0];
    const int tid = threadIdx.x;
    __shared__ float su[3072];

    const int F0 = blockIdx.x * 3072;        // first flat float of block
    float wacc = 0.0f;

    #pragma unroll
    for (int k = 0; k < 3; k++) {
        int g = (F0 >> 2) + k * 256 + tid;   // float4 index
        int flat0 = 4 * g;
        if (flat0 + 3 < n_flat) {
            float4 p = __ldcs(&pred4[g]);
            float4 f = __ldcs(&fext4[g]);
            int m = flat0 % 3;
            float ca, cb, cc;
            if (m == 0)      { ca = s0; cb = s1; cc = s2; }
            else if (m == 1) { ca = s1; cb = s2; cc = s0; }
            else             { ca = s2; cb = s0; cc = s1; }
            float u0 = p.x * ca;
            float u1 = p.y * cb;
            float u2 = p.z * cc;
            float u3 = p.w * ca;
            int loc = flat0 - F0;
            *(float4*)(su + loc) = make_float4(u0, u1, u2, u3);
            wacc += f.x * u0 + f.y * u1 + f.z * u2 + f.w * u3;
        } else if (flat0 < n_flat) {
            const float* pr = (const float*)pred4;
            const float* fe = (const float*)fext4;
            for (int j = flat0; j < n_flat; j++) {
                int m = j % 3;
                float sc = (m == 0) ? s0 : ((m == 1) ? s1 : s2);
                float u = pr[j] * sc;
                su[j - F0] = u;
                wacc += fe[j] * u;
            }
        }
    }
    __syncthreads();

    // Coalesced scalar stores to (misaligned-base) output.
    #pragma unroll
    for (int k = 0; k < 12; k++) {
        int idx = F0 + k * 256 + tid;
        if (idx < n_flat) __stcs(out_u + idx, su[idx - F0]);
    }

    // Coalesced float4 stores to g_u (stride-3 smem reads, conflict-free).
    const int Nbase = blockIdx.x * 1024;
    #pragma unroll
    for (int k = 0; k < 4; k++) {
        int ln = k * 256 + tid;
        int j = Nbase + ln;
        if (j < n_nodes)
            g_u[j] = make_float4(su[3 * ln], su[3 * ln + 1], su[3 * ln + 2], 0.0f);
    }

    double bs = block_reduce_f32_to_f64(wacc);
    if (tid == 0) g_part[blockIdx.x] = -bs;   // contributes -W
}

// ---------------- element kernel: 8 elements / thread ----------------
__global__ void __launch_bounds__(256) elem_kernel(
        const void* __restrict__ conn,
        const float* __restrict__ Lv,
        const float* __restrict__ Ev,
        const float* __restrict__ Av,
        const float* __restrict__ Iv,
        const float* __restrict__ dirs,
        int n_elem, int part_off, long long n_nodes) {

    // conn dtype probe (uniform per block; negligible cost).
    __shared__ int s_c64;
    if (threadIdx.x == 0) {
        const long long* c64 = (const long long*)conn;
        int ok = 1;
        #pragma unroll
        for (int k = 0; k < 8; k++) {
            long long v = c64[k];
            if (v < 0 || v >= n_nodes) ok = 0;
        }
        s_c64 = ok;
    }
    __syncthreads();
    const int conn64 = s_c64;

    const int i = blockIdx.x * 256 + threadIdx.x;
    const int e0 = 8 * i;
    float qacc = 0.0f;

    if (e0 < n_elem) {
        bool full = (e0 + 7 < n_elem);

        int ia[8], ib[8];
        if (conn64) {
            if (full) {
                const uint4* c = (const uint4*)((const char*)conn + (size_t)e0 * 16);
                #pragma unroll
                for (int k = 0; k < 8; k++) {
                    uint4 w = __ldcs(c + k);
                    ia[k] = (int)w.x;   // hi word is 0 for idx < 2^31
                    ib[k] = (int)w.z;
                }
            } else {
                const long long* c = (const long long*)conn;
                #pragma unroll
                for (int k = 0; k < 8; k++) {
                    int e = e0 + k;
                    if (e < n_elem) { ia[k] = (int)c[2 * (size_t)e]; ib[k] = (int)c[2 * (size_t)e + 1]; }
                    else            { ia[k] = 0; ib[k] = 0; }
                }
            }
        } else {
            if (full) {
                const uint4* c = (const uint4*)((const char*)conn + (size_t)e0 * 8);
                #pragma unroll
                for (int k = 0; k < 4; k++) {
                    uint4 w = __ldcs(c + k);
                    ia[2 * k]     = (int)w.x; ib[2 * k]     = (int)w.y;
                    ia[2 * k + 1] = (int)w.z; ib[2 * k + 1] = (int)w.w;
                }
            } else {
                const int* c = (const int*)conn;
                #pragma unroll
                for (int k = 0; k < 8; k++) {
                    int e = e0 + k;
                    if (e < n_elem) { ia[k] = c[2 * (size_t)e]; ib[k] = c[2 * (size_t)e + 1]; }
                    else            { ia[k] = 0; ib[k] = 0; }
                }
            }
        }

        // Issue all 16 gathers up front (g_u is L2-resident).
        float4 A[8], B[8];
        #pragma unroll
        for (int k = 0; k < 8; k++) {
            A[k] = g_u[ia[k]];
            B[k] = g_u[ib[k]];
        }

        float Lr[8], EAr[8], EIr[8], cr[8], sr[8];
        if (full) {
            const float4* L4p = (const float4*)(Lv + e0);
            const float4* E4p = (const float4*)(Ev + e0);
            const float4* A4p = (const float4*)(Av + e0);
            const float4* I4p = (const float4*)(Iv + e0);
            #pragma unroll
            for (int h = 0; h < 2; h++) {
                float4 L4 = __ldcs(L4p + h);
                float4 E4 = __ldcs(E4p + h);
                float4 A4 = __ldcs(A4p + h);
                float4 I4 = __ldcs(I4p + h);
                Lr[4*h+0]=L4.x; Lr[4*h+1]=L4.y; Lr[4*h+2]=L4.z; Lr[4*h+3]=L4.w;
                EAr[4*h+0]=E4.x*A4.x; EAr[4*h+1]=E4.y*A4.y;
                EAr[4*h+2]=E4.z*A4.z; EAr[4*h+3]=E4.w*A4.w;
                EIr[4*h+0]=E4.x*I4.x; EIr[4*h+1]=E4.y*I4.y;
                EIr[4*h+2]=E4.z*I4.z; EIr[4*h+3]=E4.w*I4.w;
            }
            const float4* d4 = (const float4*)dirs;   // 24 floats = 6 float4
            float4 v0 = __ldcs(&d4[6 * i + 0]);
            float4 v1 = __ldcs(&d4[6 * i + 1]);
            float4 v2 = __ldcs(&d4[6 * i + 2]);
            float4 v3 = __ldcs(&d4[6 * i + 3]);
            float4 v4 = __ldcs(&d4[6 * i + 4]);
            float4 v5 = __ldcs(&d4[6 * i + 5]);
            cr[0]=v0.x; cr[1]=v0.w; cr[2]=v1.z; cr[3]=v2.y;
            cr[4]=v3.x; cr[5]=v3.w; cr[6]=v4.z; cr[7]=v5.y;
            sr[0]=v0.z; sr[1]=v1.y; sr[2]=v2.x; sr[3]=v2.w;
            sr[4]=v3.z; sr[5]=v4.y; sr[6]=v5.x; sr[7]=v5.w;
        } else {
            #pragma unroll
            for (int k = 0; k < 8; k++) {
                int e = e0 + k;
                if (e < n_elem) {
                    float E = Ev[e];
                    Lr[k]  = Lv[e];
                    EAr[k] = E * Av[e];
                    EIr[k] = E * Iv[e];
                    cr[k]  = dirs[3 * (size_t)e + 0];
                    sr[k]  = dirs[3 * (size_t)e + 2];
                } else {
                    Lr[k] = 1.0f; EAr[k] = 0.0f; EIr[k] = 0.0f; cr[k] = 1.0f; sr[k] = 0.0f;
                }
            }
        }

        #pragma unroll
        for (int k = 0; k < 8; k++) {
            float c = cr[k], s = sr[k];
            float u_A =  c * A[k].x + s * A[k].y;
            float w_A = -s * A[k].x + c * A[k].y;
            float t_A = -A[k].z;
            float u_B =  c * B[k].x + s * B[k].y;
            float w_B = -s * B[k].x + c * B[k].y;
            float t_B = -B[k].z;

            float inv   = __fdividef(1.0f, Lr[k]);
            float ea_l  = EAr[k] * inv;
            float ei_l  = EIr[k] * inv;
            float ei_l2 = ei_l * inv;
            float ei_l3 = ei_l2 * inv;

            float du = u_A - u_B;
            float dw = w_A - w_B;
            float ts = t_A + t_B;

            float q = ea_l * du * du
                    + 12.0f * ei_l3 * dw * dw
                    + 12.0f * ei_l2 * dw * ts
                    + 4.0f * ei_l * (t_A * t_A + t_B * t_B + t_A * t_B);
            if (e0 + k < n_elem) qacc += q;
        }
    }

    double bs = block_reduce_f32_to_f64(qacc);
    if (threadIdx.x == 0) g_part[part_off + blockIdx.x] = 0.5 * bs;  // +0.5*U
}

// ---------------- final: reduce partials, normalize ----------------
__global__ void __launch_bounds__(1024) final_kernel(
        float* __restrict__ out,
        const float* __restrict__ ux_c,
        const float* __restrict__ F_c,
        int total_blocks) {
    double acc = 0.0;
    for (int k = threadIdx.x; k < total_blocks; k += 1024)
        acc += g_part[k];
    #pragma unroll
    for (int o = 16; o > 0; o >>= 1)
        acc += __shfl_xor_sync(0xffffffffu, acc, o);
    __shared__ double sh[32];
    int lane = threadIdx.x & 31;
    int wid  = threadIdx.x >> 5;
    if (lane == 0) sh[wid] = acc;
    __syncthreads();
    if (wid == 0) {
        double t = sh[lane];
        #pragma unroll
        for (int o = 16; o > 0; o >>= 1)
            t += __shfl_xor_sync(0xffffffffu, t, o);
        if (lane == 0) {
            double E_c = fmax((double)(F_c[0] * ux_c[0]), 1e-30);
            out[0] = (float)(t / E_c);
        }
    }
}

extern "C" void kernel_launch(void* const* d_in, const int* in_sizes, int n_in,
                              void* d_out, int out_size) {
    const float* pred  = (const float*)d_in[0];    // (N_NODES, 3)
    const float* fext  = (const float*)d_in[1];    // (N_NODES, 3)
    const void*  conn  = d_in[2];                  // (N_ELEM, 2) int64 or int32
    const float* Lv    = (const float*)d_in[3];
    const float* Ev    = (const float*)d_in[4];
    const float* Av    = (const float*)d_in[5];
    const float* Iv    = (const float*)d_in[6];
    const float* dirs  = (const float*)d_in[7];    // (N_ELEM, 3)
    const float* ux_c  = (const float*)d_in[8];
    const float* uz_c  = (const float*)d_in[9];
    const float* th_c  = (const float*)d_in[10];
    const float* F_c   = (const float*)d_in[11];

    float* out = (float*)d_out;   // [0] = Pi_norm, [1..3N] = u_phys flat

    int n_flat  = in_sizes[0];                // 3 * N_NODES
    int n_nodes = n_flat / 3;
    int n_elem  = in_sizes[3];                // N_ELEM

    int node_blocks = (n_flat + 3071) / 3072;              // 1024 nodes / block
    int elem_blocks = (n_elem + 8 * 256 - 1) / (8 * 256);  // 8 elems / thread
    int total_blocks = node_blocks + elem_blocks;

    node_kernel<<<node_blocks, 256>>>((const float4*)pred, (const float4*)fext,
                                      out + 1, ux_c, uz_c, th_c, n_flat, n_nodes);
    elem_kernel<<<elem_blocks, 256>>>(conn, Lv, Ev, Av, Iv, dirs,
                                      n_elem, node_blocks, (long long)n_nodes);
    final_kernel<<<1, 1024>>>(out, ux_c, F_c, total_blocks);
}